// round 3
// baseline (speedup 1.0000x reference)
#include <cuda_runtime.h>
#include <cuda_bf16.h>
#include <cstdint>

#define DEVINL __device__ __forceinline__

// ---------------- problem constants ----------------
static constexpr int D       = 512;     // feature dim
static constexpr int MAXN    = 2048;    // query rows
static constexpr int MAXK    = 65536;   // queue rows
static constexpr float INV_T = 5.0f;    // 1 / 0.2
static constexpr float QSCALE = 64.0f;  // fp8 quantization scale
static constexpr float ACC_C  = INV_T / (QSCALE * QSCALE);  // 5/4096

// GEMM tiling
static constexpr int BM = 128;          // query rows per CTA
static constexpr int BN = 256;          // queue rows per CTA
static constexpr int BK = 128;          // k-chunk (fp8) = 128 bytes/row
static constexpr int NCHUNK = D / BK;   // 4

// smem layout (dynamic): A double buf, B double buf, rowsum
static constexpr int SA_BYTES = BM * BK;              // 16384
static constexpr int SB_BYTES = BN * BK;              // 32768
static constexpr int OFF_A    = 0;                    // 2 stages
static constexpr int OFF_B    = 2 * SA_BYTES;         // 32768, 2 stages
static constexpr int OFF_ROW  = OFF_B + 2 * SB_BYTES; // 98304
static constexpr int SMEM_TOTAL = OFF_ROW + BM * 4;   // 98816

// ---------------- device scratch (static, no allocation) ----------------
static __device__ __align__(128) uint8_t g_q8[(size_t)MAXN * D];   // 1 MB  normalized query (e4m3 * 64)
static __device__ __align__(128) uint8_t g_u8[(size_t)MAXK * D];   // 32 MB normalized queue (e4m3 * 64)
static __device__ float g_lpos[MAXN];
static __device__ float g_sumexp[MAXN];

// ---------------- PTX helpers (plain sm_103 target safe) ----------------
DEVINL uint32_t smem_u32(const void* p) {
    uint32_t a;
    asm("{ .reg .u64 t; cvta.to.shared.u64 t, %1; cvt.u32.u64 %0, t; }" : "=r"(a) : "l"(p));
    return a;
}
DEVINL void cp_async_16(uint32_t sdst, const void* gsrc) {
    asm volatile("cp.async.cg.shared.global [%0], [%1], 16;" :: "r"(sdst), "l"(gsrc));
}
DEVINL void cp_commit() { asm volatile("cp.async.commit_group;" ::: "memory"); }
template <int N> DEVINL void cp_wait() {
    asm volatile("cp.async.wait_group %0;" :: "n"(N) : "memory");
}
DEVINL void ldsm_x4(uint32_t addr, uint32_t& r0, uint32_t& r1, uint32_t& r2, uint32_t& r3) {
    asm volatile("ldmatrix.sync.aligned.m8n8.x4.shared.b16 {%0,%1,%2,%3}, [%4];"
                 : "=r"(r0), "=r"(r1), "=r"(r2), "=r"(r3) : "r"(addr));
}
// FP8 e4m3 MMA: m16n8k32, fp32 accumulate
DEVINL void mma_fp8(float* d, const uint32_t* a, uint32_t b0, uint32_t b1) {
    asm volatile(
        "mma.sync.aligned.m16n8k32.row.col.f32.e4m3.e4m3.f32 "
        "{%0,%1,%2,%3}, {%4,%5,%6,%7}, {%8,%9}, {%0,%1,%2,%3};"
        : "+f"(d[0]), "+f"(d[1]), "+f"(d[2]), "+f"(d[3])
        : "r"(a[0]), "r"(a[1]), "r"(a[2]), "r"(a[3]), "r"(b0), "r"(b1));
}
// pack two floats -> e4m3x2 (result: lo byte = b, hi byte = a)
DEVINL uint16_t f2_e4m3(float hi, float lo) {
    uint16_t r;
    asm("cvt.rn.satfinite.e4m3x2.f32 %0, %1, %2;" : "=h"(r) : "f"(hi), "f"(lo));
    return r;
}
DEVINL uint32_t quant4(float x, float y, float z, float w) {
    uint32_t lo = f2_e4m3(y, x);
    uint32_t hi = f2_e4m3(w, z);
    return lo | (hi << 16);
}

// ---------------- prepass: norms, l_pos, normalized fp8 ----------------
__global__ void prep_qk_kernel(const float* __restrict__ q, const float* __restrict__ ky) {
    const int n = blockIdx.x;
    const int t = threadIdx.x;                 // 128 threads
    const float4 qv = ((const float4*)(q  + (size_t)n * D))[t];
    const float4 kv = ((const float4*)(ky + (size_t)n * D))[t];
    float sqq = qv.x*qv.x + qv.y*qv.y + qv.z*qv.z + qv.w*qv.w;
    float skk = kv.x*kv.x + kv.y*kv.y + kv.z*kv.z + kv.w*kv.w;
    float sqk = qv.x*kv.x + qv.y*kv.y + qv.z*kv.z + qv.w*kv.w;
    #pragma unroll
    for (int o = 16; o; o >>= 1) {
        sqq += __shfl_xor_sync(0xFFFFFFFFu, sqq, o);
        skk += __shfl_xor_sync(0xFFFFFFFFu, skk, o);
        sqk += __shfl_xor_sync(0xFFFFFFFFu, sqk, o);
    }
    __shared__ float sh[3][4];
    __shared__ float s_r;
    const int wid = t >> 5, lane = t & 31;
    if (lane == 0) { sh[0][wid] = sqq; sh[1][wid] = skk; sh[2][wid] = sqk; }
    __syncthreads();
    if (t == 0) {
        float a = sh[0][0] + sh[0][1] + sh[0][2] + sh[0][3];
        float b = sh[1][0] + sh[1][1] + sh[1][2] + sh[1][3];
        float c = sh[2][0] + sh[2][1] + sh[2][2] + sh[2][3];
        float qn = sqrtf(a), kn = sqrtf(b);
        float lp = c / fmaxf(qn * kn, 1e-8f) * INV_T;
        g_lpos[n]   = lp;
        g_sumexp[n] = __expf(lp);          // seed row sum with the positive logit
        s_r = QSCALE / fmaxf(qn, 1e-20f);
    }
    __syncthreads();
    const float r = s_r;
    ((uint32_t*)(g_q8 + (size_t)n * D))[t] =
        quant4(qv.x * r, qv.y * r, qv.z * r, qv.w * r);
}

__global__ void prep_u_kernel(const float* __restrict__ u) {
    const int n = blockIdx.x;
    const int t = threadIdx.x;                 // 128 threads
    const float4 v = ((const float4*)(u + (size_t)n * D))[t];
    float s = v.x*v.x + v.y*v.y + v.z*v.z + v.w*v.w;
    #pragma unroll
    for (int o = 16; o; o >>= 1) s += __shfl_xor_sync(0xFFFFFFFFu, s, o);
    __shared__ float sh[4];
    __shared__ float s_r;
    const int wid = t >> 5, lane = t & 31;
    if (lane == 0) sh[wid] = s;
    __syncthreads();
    if (t == 0) s_r = QSCALE / fmaxf(sqrtf(sh[0] + sh[1] + sh[2] + sh[3]), 1e-20f);
    __syncthreads();
    const float r = s_r;
    ((uint32_t*)(g_u8 + (size_t)n * D))[t] =
        quant4(v.x * r, v.y * r, v.z * r, v.w * r);
}

// ---------------- fused GEMM + exp-rowsum (FP8 QMMA path) ----------------
// 256 threads = 8 warps laid out 2(M) x 4(N); each warp computes 64x64.
// smem rows are 128B (128 fp8), swizzled in 16B chunks: kc' = kc ^ (row & 7).

DEVINL void load_tiles(int c, uint32_t sA, uint32_t sB, int m0, int n0, int t) {
    const int koff = c * BK;
    #pragma unroll
    for (int i = 0; i < 4; i++) {                       // A: 1024 16B lines
        int idx = t + i * 256;
        int row = idx >> 3, kc = idx & 7;
        const void* g = g_q8 + (((size_t)(m0 + row)) << 9) + koff + (kc << 4);
        cp_async_16(sA + row * 128 + ((kc ^ (row & 7)) << 4), g);
    }
    #pragma unroll
    for (int i = 0; i < 8; i++) {                       // B: 2048 16B lines
        int idx = t + i * 256;
        int row = idx >> 3, kc = idx & 7;
        const void* g = g_u8 + (((size_t)(n0 + row)) << 9) + koff + (kc << 4);
        cp_async_16(sB + row * 128 + ((kc ^ (row & 7)) << 4), g);
    }
}

__global__ __launch_bounds__(256, 1) void gemm_lse_kernel() {
    extern __shared__ char smem[];
    const uint32_t sb = smem_u32(smem);
    const int t = threadIdx.x, wid = t >> 5, lane = t & 31;
    const int m0 = blockIdx.x * BM;        // x fastest: m-tiles of one n-tile co-run -> B L2 reuse
    const int n0 = blockIdx.y * BN;
    const int wm = (wid >> 2) * 64;        // warp m offset within tile
    const int wn = (wid & 3) * 64;         // warp n offset within tile

    float* srow = (float*)(smem + OFF_ROW);
    if (t < BM) srow[t] = 0.0f;

    float acc[4][8][4];
    #pragma unroll
    for (int mi = 0; mi < 4; mi++)
        #pragma unroll
        for (int ni = 0; ni < 8; ni++)
            #pragma unroll
            for (int j = 0; j < 4; j++) acc[mi][ni][j] = 0.0f;

    // per-lane ldmatrix address components (16B granules along k)
    // A (m16 x k32): lanes 0-15 -> rows 0-15 @ kc, lanes 16-31 -> rows 0-15 @ kc+1
    const int arow = lane & 15;
    const int akc  = lane >> 4;
    // B (n16 x k32): lanes 0-7 cols 0-7 @ kc; 8-15 cols 0-7 @ kc+1; 16-23 cols 8-15 @ kc; 24-31 @ kc+1
    const int brow = (lane & 7) | ((lane & 16) >> 1);
    const int bkc  = (lane >> 3) & 1;

    const uint32_t sA[2] = { sb + OFF_A, sb + OFF_A + SA_BYTES };
    const uint32_t sB[2] = { sb + OFF_B, sb + OFF_B + SB_BYTES };

    load_tiles(0, sA[0], sB[0], m0, n0, t);
    cp_commit();

    #pragma unroll 1
    for (int c = 0; c < NCHUNK; ++c) {
        if (c + 1 < NCHUNK) {
            load_tiles(c + 1, sA[(c + 1) & 1], sB[(c + 1) & 1], m0, n0, t);
            cp_commit();
            cp_wait<1>();
        } else {
            cp_wait<0>();
        }
        __syncthreads();

        const uint32_t a_base = sA[c & 1];
        const uint32_t b_base = sB[c & 1];
        #pragma unroll
        for (int ks = 0; ks < 4; ++ks) {        // 4 x k32 per 128B chunk
            uint32_t af[4][4];
            #pragma unroll
            for (int mi = 0; mi < 4; mi++) {
                int row = wm + mi * 16 + arow;
                int kc  = ks * 2 + akc;
                ldsm_x4(a_base + row * 128 + ((kc ^ (row & 7)) << 4),
                        af[mi][0], af[mi][1], af[mi][2], af[mi][3]);
            }
            uint32_t bf[4][4];
            #pragma unroll
            for (int nj = 0; nj < 4; nj++) {
                int row = wn + nj * 16 + brow;
                int kc  = ks * 2 + bkc;
                ldsm_x4(b_base + row * 128 + ((kc ^ (row & 7)) << 4),
                        bf[nj][0], bf[nj][1], bf[nj][2], bf[nj][3]);
            }
            // bf[nj] = {cols0-7 k0-15, cols0-7 k16-31, cols8-15 k0-15, cols8-15 k16-31}
            #pragma unroll
            for (int mi = 0; mi < 4; mi++)
                #pragma unroll
                for (int ni = 0; ni < 8; ni++) {
                    const int nj = ni >> 1, h = (ni & 1) << 1;
                    mma_fp8(acc[mi][ni], af[mi], bf[nj][h], bf[nj][h + 1]);
                }
        }
        __syncthreads();
    }

    // ---------- epilogue: exp + row-sum ----------
    #pragma unroll
    for (int mi = 0; mi < 4; mi++) {
        float r0 = 0.0f, r1 = 0.0f;
        #pragma unroll
        for (int ni = 0; ni < 8; ni++) {
            r0 += __expf(acc[mi][ni][0] * ACC_C) + __expf(acc[mi][ni][1] * ACC_C);
            r1 += __expf(acc[mi][ni][2] * ACC_C) + __expf(acc[mi][ni][3] * ACC_C);
        }
        r0 += __shfl_xor_sync(0xFFFFFFFFu, r0, 1);
        r0 += __shfl_xor_sync(0xFFFFFFFFu, r0, 2);
        r1 += __shfl_xor_sync(0xFFFFFFFFu, r1, 1);
        r1 += __shfl_xor_sync(0xFFFFFFFFu, r1, 2);
        if ((lane & 3) == 0) {
            atomicAdd(&srow[wm + mi * 16 + (lane >> 2)], r0);
            atomicAdd(&srow[wm + mi * 16 + (lane >> 2) + 8], r1);
        }
    }
    __syncthreads();
    if (t < BM) atomicAdd(&g_sumexp[m0 + t], srow[t]);
}

// ---------------- final reduction ----------------
__global__ void finalize_kernel(float* __restrict__ out, int N) {
    const int t = threadIdx.x;   // 256
    float s = 0.0f;
    for (int i = t; i < N; i += 256) s += logf(g_sumexp[i]) - g_lpos[i];
    #pragma unroll
    for (int o = 16; o; o >>= 1) s += __shfl_xor_sync(0xFFFFFFFFu, s, o);
    __shared__ float sh[8];
    if ((t & 31) == 0) sh[t >> 5] = s;
    __syncthreads();
    if (t == 0) {
        float tot = 0.0f;
        #pragma unroll
        for (int i = 0; i < 8; i++) tot += sh[i];
        out[0] = tot / (float)N;
    }
}

// ---------------- launch ----------------
extern "C" void kernel_launch(void* const* d_in, const int* in_sizes, int n_in,
                              void* d_out, int out_size) {
    const float* q = (const float*)d_in[0];
    const float* k = (const float*)d_in[1];
    const float* u = (const float*)d_in[2];
    const int N = in_sizes[0] / D;   // 2048
    const int K = in_sizes[2] / D;   // 65536

    prep_qk_kernel<<<N, 128>>>(q, k);
    prep_u_kernel<<<K, 128>>>(u);

    cudaFuncSetAttribute(gemm_lse_kernel, cudaFuncAttributeMaxDynamicSharedMemorySize, SMEM_TOTAL);
    dim3 grid(N / BM, K / BN);
    gemm_lse_kernel<<<grid, 256, SMEM_TOTAL>>>();

    finalize_kernel<<<1, 256>>>((float*)d_out, N);
}

// round 4
// speedup vs baseline: 1.2126x; 1.2126x over previous
#include <cuda_runtime.h>
#include <cuda_bf16.h>
#include <cstdint>

#define DEVINL __device__ __forceinline__

// ---------------- problem constants ----------------
static constexpr int D       = 512;     // feature dim
static constexpr int MAXN    = 2048;    // query rows
static constexpr int MAXK    = 65536;   // queue rows
static constexpr float INV_T = 5.0f;    // 1 / 0.2

// GEMM tiling
static constexpr int BM = 128;          // query rows per CTA
static constexpr int BN = 128;          // queue rows per CTA
static constexpr int BK = 64;           // k-chunk (bf16) = 128 bytes/row
static constexpr int NCHUNK = D / BK;   // 8
static constexpr int NSTAGE = 3;

// smem layout (dynamic): 3 stages of (A,B), then rowsum
static constexpr int SA_BYTES = BM * BK * 2;          // 16384
static constexpr int SB_BYTES = BN * BK * 2;          // 16384
static constexpr int STAGE_BYTES = SA_BYTES + SB_BYTES;        // 32768
static constexpr int OFF_ROW  = NSTAGE * STAGE_BYTES;          // 98304
static constexpr int SMEM_TOTAL = OFF_ROW + BM * 4;            // 98816

// ---------------- device scratch (static, no allocation) ----------------
static __device__ __align__(128) __nv_bfloat16 g_qbf[(size_t)MAXN * D];   // 2 MB normalized query
static __device__ __align__(128) __nv_bfloat16 g_ubf[(size_t)MAXK * D];   // 64 MB normalized queue
static __device__ float g_lpos[MAXN];
static __device__ float g_sumexp[MAXN];

// ---------------- PTX helpers (plain sm_103 target safe) ----------------
DEVINL uint32_t smem_u32(const void* p) {
    uint32_t a;
    asm("{ .reg .u64 t; cvta.to.shared.u64 t, %1; cvt.u32.u64 %0, t; }" : "=r"(a) : "l"(p));
    return a;
}
DEVINL void cp_async_16(uint32_t sdst, const void* gsrc) {
    asm volatile("cp.async.cg.shared.global [%0], [%1], 16;" :: "r"(sdst), "l"(gsrc));
}
DEVINL void cp_commit() { asm volatile("cp.async.commit_group;" ::: "memory"); }
template <int N> DEVINL void cp_wait() {
    asm volatile("cp.async.wait_group %0;" :: "n"(N) : "memory");
}
DEVINL void ldsm_x4(uint32_t addr, uint32_t& r0, uint32_t& r1, uint32_t& r2, uint32_t& r3) {
    asm volatile("ldmatrix.sync.aligned.m8n8.x4.shared.b16 {%0,%1,%2,%3}, [%4];"
                 : "=r"(r0), "=r"(r1), "=r"(r2), "=r"(r3) : "r"(addr));
}
DEVINL void mma16816(float* d, const uint32_t* a, uint32_t b0, uint32_t b1) {
    asm volatile(
        "mma.sync.aligned.m16n8k16.row.col.f32.bf16.bf16.f32 "
        "{%0,%1,%2,%3}, {%4,%5,%6,%7}, {%8,%9}, {%0,%1,%2,%3};"
        : "+f"(d[0]), "+f"(d[1]), "+f"(d[2]), "+f"(d[3])
        : "r"(a[0]), "r"(a[1]), "r"(a[2]), "r"(a[3]), "r"(b0), "r"(b1));
}

// ---------------- prepass: norms, l_pos, normalized bf16 ----------------
__global__ void prep_qk_kernel(const float* __restrict__ q, const float* __restrict__ ky) {
    const int n = blockIdx.x;
    const int t = threadIdx.x;                 // 128 threads
    const float4 qv = ((const float4*)(q  + (size_t)n * D))[t];
    const float4 kv = ((const float4*)(ky + (size_t)n * D))[t];
    float sqq = qv.x*qv.x + qv.y*qv.y + qv.z*qv.z + qv.w*qv.w;
    float skk = kv.x*kv.x + kv.y*kv.y + kv.z*kv.z + kv.w*kv.w;
    float sqk = qv.x*kv.x + qv.y*kv.y + qv.z*kv.z + qv.w*kv.w;
    #pragma unroll
    for (int o = 16; o; o >>= 1) {
        sqq += __shfl_xor_sync(0xFFFFFFFFu, sqq, o);
        skk += __shfl_xor_sync(0xFFFFFFFFu, skk, o);
        sqk += __shfl_xor_sync(0xFFFFFFFFu, sqk, o);
    }
    __shared__ float sh[3][4];
    __shared__ float s_r;
    const int wid = t >> 5, lane = t & 31;
    if (lane == 0) { sh[0][wid] = sqq; sh[1][wid] = skk; sh[2][wid] = sqk; }
    __syncthreads();
    if (t == 0) {
        float a = sh[0][0] + sh[0][1] + sh[0][2] + sh[0][3];
        float b = sh[1][0] + sh[1][1] + sh[1][2] + sh[1][3];
        float c = sh[2][0] + sh[2][1] + sh[2][2] + sh[2][3];
        float qn = sqrtf(a), kn = sqrtf(b);
        float lp = c / fmaxf(qn * kn, 1e-8f) * INV_T;
        g_lpos[n]   = lp;
        g_sumexp[n] = __expf(lp);          // seed row sum with the positive logit
        s_r = 1.0f / fmaxf(qn, 1e-20f);
    }
    __syncthreads();
    const float r = s_r;
    __nv_bfloat162* dst = (__nv_bfloat162*)(g_qbf + (size_t)n * D);
    dst[2*t]     = __floats2bfloat162_rn(qv.x * r, qv.y * r);
    dst[2*t + 1] = __floats2bfloat162_rn(qv.z * r, qv.w * r);
}

__global__ void prep_u_kernel(const float* __restrict__ u) {
    const int n = blockIdx.x;
    const int t = threadIdx.x;                 // 128 threads
    const float4 v = ((const float4*)(u + (size_t)n * D))[t];
    float s = v.x*v.x + v.y*v.y + v.z*v.z + v.w*v.w;
    #pragma unroll
    for (int o = 16; o; o >>= 1) s += __shfl_xor_sync(0xFFFFFFFFu, s, o);
    __shared__ float sh[4];
    __shared__ float s_r;
    const int wid = t >> 5, lane = t & 31;
    if (lane == 0) sh[wid] = s;
    __syncthreads();
    if (t == 0) s_r = 1.0f / fmaxf(sqrtf(sh[0] + sh[1] + sh[2] + sh[3]), 1e-20f);
    __syncthreads();
    const float r = s_r;
    __nv_bfloat162* dst = (__nv_bfloat162*)(g_ubf + (size_t)n * D);
    dst[2*t]     = __floats2bfloat162_rn(v.x * r, v.y * r);
    dst[2*t + 1] = __floats2bfloat162_rn(v.z * r, v.w * r);
}

// ---------------- fused GEMM + exp-rowsum (HMMA, 3-stage, occ=2) ----------------
// 256 threads = 8 warps laid out 2(M) x 4(N); each warp computes 64x32.
// smem rows are 128B (64 bf16), swizzled in 16B chunks: kc' = kc ^ (row & 7).

DEVINL void load_tiles(int c, uint32_t sA, uint32_t sB, int m0, int n0, int t) {
    const int koff = c * BK;
    #pragma unroll
    for (int i = 0; i < 4; i++) {                       // A: 1024 16B lines
        int idx = t + i * 256;
        int row = idx >> 3, kc = idx & 7;
        const void* g = g_qbf + (((size_t)(m0 + row)) << 9) + koff + (kc << 3);
        cp_async_16(sA + row * 128 + ((kc ^ (row & 7)) << 4), g);
    }
    #pragma unroll
    for (int i = 0; i < 4; i++) {                       // B: 1024 16B lines
        int idx = t + i * 256;
        int row = idx >> 3, kc = idx & 7;
        const void* g = g_ubf + (((size_t)(n0 + row)) << 9) + koff + (kc << 3);
        cp_async_16(sB + row * 128 + ((kc ^ (row & 7)) << 4), g);
    }
}

__global__ __launch_bounds__(256, 2) void gemm_lse_kernel() {
    extern __shared__ char smem[];
    const uint32_t sb = smem_u32(smem);
    const int t = threadIdx.x, wid = t >> 5, lane = t & 31;
    const int m0 = blockIdx.x * BM;        // x fastest: m-tiles of one n-tile co-run -> B L2 reuse
    const int n0 = blockIdx.y * BN;
    const int wm = (wid >> 2) * 64;        // warp m offset within tile
    const int wn = (wid & 3) * 32;         // warp n offset within tile

    float* srow = (float*)(smem + OFF_ROW);
    if (t < BM) srow[t] = 0.0f;

    float acc[4][4][4];
    #pragma unroll
    for (int mi = 0; mi < 4; mi++)
        #pragma unroll
        for (int ni = 0; ni < 4; ni++)
            #pragma unroll
            for (int j = 0; j < 4; j++) acc[mi][ni][j] = 0.0f;

    // per-lane ldmatrix address components (16B granules along k)
    const int arow = lane & 15;
    const int akc  = lane >> 4;
    const int brow = (lane & 7) | ((lane & 16) >> 1);
    const int bkc  = (lane >> 3) & 1;

    uint32_t bufA[NSTAGE], bufB[NSTAGE];
    #pragma unroll
    for (int s = 0; s < NSTAGE; s++) {
        bufA[s] = sb + s * STAGE_BYTES;
        bufB[s] = sb + s * STAGE_BYTES + SA_BYTES;
    }

    load_tiles(0, bufA[0], bufB[0], m0, n0, t);
    cp_commit();
    load_tiles(1, bufA[1], bufB[1], m0, n0, t);
    cp_commit();

    #pragma unroll 1
    for (int c = 0; c < NCHUNK; ++c) {
        if (c < NCHUNK - 1) cp_wait<1>(); else cp_wait<0>();
        __syncthreads();                       // chunk c visible; all warps done with chunk c-1

        if (c + 2 < NCHUNK) {                  // prefetch into the stage holding chunk c-1
            const int s = (c + 2) % NSTAGE;
            load_tiles(c + 2, bufA[s], bufB[s], m0, n0, t);
            cp_commit();
        }

        const uint32_t a_base = bufA[c % NSTAGE];
        const uint32_t b_base = bufB[c % NSTAGE];
        #pragma unroll
        for (int ks = 0; ks < 4; ++ks) {
            uint32_t af[4][4];
            #pragma unroll
            for (int mi = 0; mi < 4; mi++) {
                int row = wm + mi * 16 + arow;
                int kc  = ks * 2 + akc;
                ldsm_x4(a_base + row * 128 + ((kc ^ (row & 7)) << 4),
                        af[mi][0], af[mi][1], af[mi][2], af[mi][3]);
            }
            uint32_t bf[2][4];
            #pragma unroll
            for (int nj = 0; nj < 2; nj++) {
                int row = wn + nj * 16 + brow;
                int kc  = ks * 2 + bkc;
                ldsm_x4(b_base + row * 128 + ((kc ^ (row & 7)) << 4),
                        bf[nj][0], bf[nj][1], bf[nj][2], bf[nj][3]);
            }
            #pragma unroll
            for (int mi = 0; mi < 4; mi++)
                #pragma unroll
                for (int ni = 0; ni < 4; ni++) {
                    const int nj = ni >> 1, h = (ni & 1) << 1;
                    mma16816(acc[mi][ni], af[mi], bf[nj][h], bf[nj][h + 1]);
                }
        }
    }
    __syncthreads();

    // ---------- epilogue: exp + row-sum ----------
    #pragma unroll
    for (int mi = 0; mi < 4; mi++) {
        float r0 = 0.0f, r1 = 0.0f;
        #pragma unroll
        for (int ni = 0; ni < 4; ni++) {
            r0 += __expf(acc[mi][ni][0] * INV_T) + __expf(acc[mi][ni][1] * INV_T);
            r1 += __expf(acc[mi][ni][2] * INV_T) + __expf(acc[mi][ni][3] * INV_T);
        }
        r0 += __shfl_xor_sync(0xFFFFFFFFu, r0, 1);
        r0 += __shfl_xor_sync(0xFFFFFFFFu, r0, 2);
        r1 += __shfl_xor_sync(0xFFFFFFFFu, r1, 1);
        r1 += __shfl_xor_sync(0xFFFFFFFFu, r1, 2);
        if ((lane & 3) == 0) {
            atomicAdd(&srow[wm + mi * 16 + (lane >> 2)], r0);
            atomicAdd(&srow[wm + mi * 16 + (lane >> 2) + 8], r1);
        }
    }
    __syncthreads();
    if (t < BM) atomicAdd(&g_sumexp[m0 + t], srow[t]);
}

// ---------------- final reduction ----------------
__global__ void finalize_kernel(float* __restrict__ out, int N) {
    const int t = threadIdx.x;   // 256
    float s = 0.0f;
    for (int i = t; i < N; i += 256) s += logf(g_sumexp[i]) - g_lpos[i];
    #pragma unroll
    for (int o = 16; o; o >>= 1) s += __shfl_xor_sync(0xFFFFFFFFu, s, o);
    __shared__ float sh[8];
    if ((t & 31) == 0) sh[t >> 5] = s;
    __syncthreads();
    if (t == 0) {
        float tot = 0.0f;
        #pragma unroll
        for (int i = 0; i < 8; i++) tot += sh[i];
        out[0] = tot / (float)N;
    }
}

// ---------------- launch ----------------
extern "C" void kernel_launch(void* const* d_in, const int* in_sizes, int n_in,
                              void* d_out, int out_size) {
    const float* q = (const float*)d_in[0];
    const float* k = (const float*)d_in[1];
    const float* u = (const float*)d_in[2];
    const int N = in_sizes[0] / D;   // 2048
    const int K = in_sizes[2] / D;   // 65536

    prep_qk_kernel<<<N, 128>>>(q, k);
    prep_u_kernel<<<K, 128>>>(u);

    cudaFuncSetAttribute(gemm_lse_kernel, cudaFuncAttributeMaxDynamicSharedMemorySize, SMEM_TOTAL);
    dim3 grid(N / BM, K / BN);
    gemm_lse_kernel<<<grid, 256, SMEM_TOTAL>>>();

    finalize_kernel<<<1, 256>>>((float*)d_out, N);
}